// round 1
// baseline (speedup 1.0000x reference)
#include <cuda_runtime.h>
#include <cuda_bf16.h>
#include <cstdint>

// -------------------------------------------------------------------------
// CoralFocalLoss_MultiTask: three CORAL focal losses over N=2e6 samples.
//
// Per element (logit x, binary coral target tm):
//   loss = alpha(tm) * h(y),  y = tm ? x : -x,  alpha = tm ? 0.25 : 0.75
//   h(y) = sigmoid(-y)^2 * softplus(-y) = u^2 * (s - y)
//      t = e^y, u = 1/(1+t), s = log(1+t)
// Row loss scaled by class_weights[kl_t]. Outputs are means.
//
// 2 MUFU (EX2, LG2) per logit; reciprocal done on FMA pipe via bit trick +
// 2 Newton iterations (rel err ~6e-6, one-sided; negligible vs 1e-3 tol).
// -------------------------------------------------------------------------

#define NBLOCKS 1184
#define NTHREADS 256

__device__ float g_partials[NBLOCKS * 3];

__device__ __forceinline__ float fast_rcp(float a) {
    // valid for a in [1, ~1e6]; here a = 1 + e^y >= 1
    float u = __int_as_float(0x7EF311C3 - __float_as_int(a));
    u = u * (2.0f - a * u);
    u = u * (2.0f - a * u);
    return u;
}

__device__ __forceinline__ float coral_term(float x, bool tm) {
    float y     = tm ? x : -x;
    float alpha = tm ? 0.25f : 0.75f;
    float t = __expf(y);           // EX2 (+mul)
    float a = 1.0f + t;
    float u = fast_rcp(a);         // FMA pipe
    float s = __logf(a);           // LG2 (+mul)
    return alpha * (u * u) * (s - y);
}

__global__ void __launch_bounds__(NTHREADS)
coral_main_kernel(const float* __restrict__ kl_logits,
                  const float* __restrict__ jsnm_logits,
                  const float* __restrict__ jsnl_logits,
                  const float* __restrict__ class_weights,
                  const int*   __restrict__ kl_t,
                  const int*   __restrict__ jsnm_t,
                  const int*   __restrict__ jsnl_t,
                  int n)
{
    __shared__ float s_w[5];
    if (threadIdx.x < 5) s_w[threadIdx.x] = class_weights[threadIdx.x];
    __syncthreads();

    float sum_kl = 0.0f, sum_m = 0.0f, sum_l = 0.0f;

    int stride = gridDim.x * blockDim.x;
    for (int i = blockIdx.x * blockDim.x + threadIdx.x; i < n; i += stride) {
        int kt = kl_t[i];
        int mt = jsnm_t[i];
        int lt = jsnl_t[i];
        float w = s_w[kt];

        float4 q = reinterpret_cast<const float4*>(kl_logits)[i];
        float rk = coral_term(q.x, 0 < kt)
                 + coral_term(q.y, 1 < kt)
                 + coral_term(q.z, 2 < kt)
                 + coral_term(q.w, 3 < kt);
        sum_kl += w * rk;

        const float* pm = jsnm_logits + 3 * (size_t)i;
        float rm = coral_term(pm[0], 0 < mt)
                 + coral_term(pm[1], 1 < mt)
                 + coral_term(pm[2], 2 < mt);
        sum_m += w * rm;

        const float* pl = jsnl_logits + 3 * (size_t)i;
        float rl = coral_term(pl[0], 0 < lt)
                 + coral_term(pl[1], 1 < lt)
                 + coral_term(pl[2], 2 < lt);
        sum_l += w * rl;
    }

    // deterministic block reduction: warp shuffle, then shared across warps
    const unsigned FULL = 0xFFFFFFFFu;
    #pragma unroll
    for (int o = 16; o > 0; o >>= 1) {
        sum_kl += __shfl_down_sync(FULL, sum_kl, o);
        sum_m  += __shfl_down_sync(FULL, sum_m,  o);
        sum_l  += __shfl_down_sync(FULL, sum_l,  o);
    }

    __shared__ float s_red[3][NTHREADS / 32];
    int wid = threadIdx.x >> 5;
    int lid = threadIdx.x & 31;
    if (lid == 0) {
        s_red[0][wid] = sum_kl;
        s_red[1][wid] = sum_m;
        s_red[2][wid] = sum_l;
    }
    __syncthreads();

    if (wid == 0) {
        float v0 = (lid < NTHREADS / 32) ? s_red[0][lid] : 0.0f;
        float v1 = (lid < NTHREADS / 32) ? s_red[1][lid] : 0.0f;
        float v2 = (lid < NTHREADS / 32) ? s_red[2][lid] : 0.0f;
        #pragma unroll
        for (int o = 4; o > 0; o >>= 1) {
            v0 += __shfl_down_sync(FULL, v0, o);
            v1 += __shfl_down_sync(FULL, v1, o);
            v2 += __shfl_down_sync(FULL, v2, o);
        }
        if (lid == 0) {
            g_partials[blockIdx.x * 3 + 0] = v0;
            g_partials[blockIdx.x * 3 + 1] = v1;
            g_partials[blockIdx.x * 3 + 2] = v2;
        }
    }
}

__global__ void __launch_bounds__(NTHREADS)
coral_finalize_kernel(float* __restrict__ out, int nblocks, int n)
{
    float v0 = 0.0f, v1 = 0.0f, v2 = 0.0f;
    for (int i = threadIdx.x; i < nblocks; i += NTHREADS) {
        v0 += g_partials[i * 3 + 0];
        v1 += g_partials[i * 3 + 1];
        v2 += g_partials[i * 3 + 2];
    }
    const unsigned FULL = 0xFFFFFFFFu;
    #pragma unroll
    for (int o = 16; o > 0; o >>= 1) {
        v0 += __shfl_down_sync(FULL, v0, o);
        v1 += __shfl_down_sync(FULL, v1, o);
        v2 += __shfl_down_sync(FULL, v2, o);
    }
    __shared__ float s_red[3][NTHREADS / 32];
    int wid = threadIdx.x >> 5;
    int lid = threadIdx.x & 31;
    if (lid == 0) {
        s_red[0][wid] = v0;
        s_red[1][wid] = v1;
        s_red[2][wid] = v2;
    }
    __syncthreads();
    if (threadIdx.x == 0) {
        float t0 = 0.0f, t1 = 0.0f, t2 = 0.0f;
        #pragma unroll
        for (int i = 0; i < NTHREADS / 32; i++) {
            t0 += s_red[0][i];
            t1 += s_red[1][i];
            t2 += s_red[2][i];
        }
        float l_kl   = t0 / (4.0f * (float)n);
        float l_jsnm = t1 / (3.0f * (float)n);
        float l_jsnl = t2 / (3.0f * (float)n);
        float total  = (l_kl + l_jsnm + l_jsnl) * (1.0f / 3.0f);
        out[0] = total;
        out[1] = l_kl;
        out[2] = l_jsnm;
        out[3] = l_jsnl;
    }
}

extern "C" void kernel_launch(void* const* d_in, const int* in_sizes, int n_in,
                              void* d_out, int out_size)
{
    const float* kl_logits     = (const float*)d_in[0];
    const float* jsnm_logits   = (const float*)d_in[1];
    const float* jsnl_logits   = (const float*)d_in[2];
    const float* class_weights = (const float*)d_in[3];
    const int*   kl_t          = (const int*)d_in[4];
    const int*   jsnm_t        = (const int*)d_in[5];
    const int*   jsnl_t        = (const int*)d_in[6];

    int n = in_sizes[4];  // N samples (kl_t element count)

    coral_main_kernel<<<NBLOCKS, NTHREADS>>>(
        kl_logits, jsnm_logits, jsnl_logits, class_weights,
        kl_t, jsnm_t, jsnl_t, n);

    coral_finalize_kernel<<<1, NTHREADS>>>((float*)d_out, NBLOCKS, n);
}